// round 6
// baseline (speedup 1.0000x reference)
#include <cuda_runtime.h>

// Shapes (fixed by the reference):
//   x      [64, 512, 56, 56]  fp32 ; ssty [64, 512, 3, 3] ; beta [1]
//   conv_w [512, 512, 3, 3]   ; conv_b [512]
// out = x * mask[c],  mask = sigmoid(beta * (dot(sum_b ssty, conv_w[c]) + conv_b[c]))

#define C_CH     512
#define KVOL4    1152                       // 512*3*3 / 4
#define NTOT     (64u * 512u * 56u * 56u)   // 102,760,448
#define N4       (NTOT / 4u)                // 25,690,112
#define HW4      784u                       // 3136/4
#define NBLK     (N4 / 1024u)               // 25088
#define RED_BLKS 36u
#define DOT_BLKS 512u

__device__ float4   g_s4[KVOL4];
__device__ float    g_mask[C_CH];
__device__ unsigned g_ctr1;   // reduce-done count   (zero-init, self-resetting)
__device__ unsigned g_ctr2;   // dot-done count
__device__ unsigned g_ctr3;   // block-retire count

__device__ __forceinline__ void spin_ge(volatile unsigned* p, unsigned tgt) {
    if (threadIdx.x == 0) {
        while (*p < tgt) __nanosleep(32);
        __threadfence();
    }
    __syncthreads();
}

__global__ void __launch_bounds__(256, 8)
fused_kernel(const float4* __restrict__ x,
             const float4* __restrict__ ssty4,
             const float*  __restrict__ beta,
             const float4* __restrict__ conv_w4,
             const float*  __restrict__ conv_b,
             float4* __restrict__ out,
             float*  __restrict__ mask_tail,
             int write_tail) {
    const unsigned bid = blockIdx.x;
    const int      tid = threadIdx.x;

    if (bid < RED_BLKS) {
        // ── Role A: s[j] = sum_b ssty[b, j] ──
        const int lane = tid & 31, grp = tid >> 5;
        const int j4 = bid * 32 + lane;
        float4 acc = make_float4(0.f, 0.f, 0.f, 0.f);
        #pragma unroll
        for (int b = 0; b < 8; ++b) {
            float4 v = ssty4[(grp * 8 + b) * KVOL4 + j4];
            acc.x += v.x; acc.y += v.y; acc.z += v.z; acc.w += v.w;
        }
        __shared__ float4 redA[8][32];
        redA[grp][lane] = acc;
        __syncthreads();
        if (grp == 0) {
            float4 t = redA[0][lane];
            #pragma unroll
            for (int p = 1; p < 8; ++p) {
                float4 v = redA[p][lane];
                t.x += v.x; t.y += v.y; t.z += v.z; t.w += v.w;
            }
            g_s4[j4] = t;
        }
        __syncthreads();
        if (tid == 0) { __threadfence(); atomicAdd(&g_ctr1, 1u); }
    } else if (bid < RED_BLKS + DOT_BLKS) {
        // ── Role B: mask[c] = sigmoid(beta*(dot(s, w_c) + b_c)) ──
        // No register prefetch: keeps regs <=32 so stream occupancy is intact.
        const int c = bid - RED_BLKS;
        const float4* __restrict__ w4 = conv_w4 + (size_t)c * KVOL4;

        spin_ge(&g_ctr1, RED_BLKS);

        float acc = 0.0f;
        #pragma unroll
        for (int k = 0; k < 5; ++k) {
            int j = tid + k * 256;
            if (j < KVOL4) {
                float4 w = w4[j];
                float4 s = g_s4[j];
                acc += w.x * s.x + w.y * s.y + w.z * s.z + w.w * s.w;
            }
        }
        #pragma unroll
        for (int off = 16; off > 0; off >>= 1)
            acc += __shfl_down_sync(0xFFFFFFFFu, acc, off);
        __shared__ float redB[8];
        if ((tid & 31) == 0) redB[tid >> 5] = acc;
        __syncthreads();
        if (tid == 0) {
            float s = 0.0f;
            #pragma unroll
            for (int i = 0; i < 8; ++i) s += redB[i];
            float m   = (s + conv_b[c]) * beta[0];
            float msk = 1.0f / (1.0f + expf(-m));
            g_mask[c] = msk;
            if (write_tail) mask_tail[c] = msk;
            __threadfence();
            atomicAdd(&g_ctr2, 1u);
        }
    }

    // ── Role C (every block): out = x * mask[channel] over tile `bid` ──
    spin_ge(&g_ctr2, DOT_BLKS);

    const unsigned base = bid * 1024u + tid;
    #pragma unroll
    for (int k = 0; k < 4; ++k) {
        unsigned i = base + k * 256u;
        unsigned c = (i / HW4) & (C_CH - 1);
        float m = g_mask[c];
        float4 v = __ldcs(x + i);
        v.x *= m; v.y *= m; v.z *= m; v.w *= m;
        __stcs(out + i, v);
    }

    // ── Self-reset for graph replay: last block out zeroes the counters. ──
    if (tid == 0) {
        if (atomicAdd(&g_ctr3, 1u) == NBLK - 1u) {
            __threadfence();
            g_ctr1 = 0; g_ctr2 = 0; g_ctr3 = 0;
        }
    }
}

extern "C" void kernel_launch(void* const* d_in, const int* in_sizes, int n_in,
                              void* d_out, int out_size) {
    const float* x      = (const float*)d_in[0];
    const float* ssty   = (const float*)d_in[1];
    const float* beta   = (const float*)d_in[2];
    const float* conv_w = (const float*)d_in[3];
    const float* conv_b = (const float*)d_in[4];
    float* out = (float*)d_out;

    int write_tail = (out_size > (int)NTOT) ? 1 : 0;

    fused_kernel<<<NBLK, 256>>>((const float4*)x, (const float4*)ssty, beta,
                                (const float4*)conv_w, conv_b,
                                (float4*)out, out + NTOT, write_tail);
}

// round 7
// speedup vs baseline: 1.0842x; 1.0842x over previous
#include <cuda_runtime.h>

// Shapes (fixed by the reference):
//   x      [64, 512, 56, 56]  fp32 ; ssty [64, 512, 3, 3] ; beta [1]
//   conv_w [512, 512, 3, 3]   ; conv_b [512]
// out = x * mask[c],  mask = sigmoid(beta * (dot(sum_b ssty, conv_w[c]) + conv_b[c]))

#define C_CH    512
#define KVOL4   1152                       // 512*3*3 / 4
#define NTOT    (64u * 512u * 56u * 56u)   // 102,760,448
#define N4      (NTOT / 4u)                // 25,690,112
#define HW4     784u                       // 3136/4
#define RED_BLKS 36
#define DOT_BLKS 512

__device__ float4   g_s4[KVOL4];
__device__ float    g_mask[C_CH];
__device__ unsigned g_ctr1;               // zero-initialized; reset post-PDL-sync

// ── Kernel 1: reduce + dot fused, 548 blocks = one wave (R5, proven) ─────────
__global__ void __launch_bounds__(256)
mask_kernel(const float4* __restrict__ ssty4,
            const float*  __restrict__ beta,
            const float4* __restrict__ conv_w4,
            const float*  __restrict__ conv_b,
            float* __restrict__ mask_tail,
            int write_tail) {
    const unsigned bid = blockIdx.x;
    const int      tid = threadIdx.x;

    if (bid < RED_BLKS) {
        // Role A: s[j] = sum_b ssty[b, j]
        const int lane = tid & 31, grp = tid >> 5;
        const int j4 = bid * 32 + lane;
        float4 acc = make_float4(0.f, 0.f, 0.f, 0.f);
        #pragma unroll
        for (int b = 0; b < 8; ++b) {
            float4 v = ssty4[(grp * 8 + b) * KVOL4 + j4];
            acc.x += v.x; acc.y += v.y; acc.z += v.z; acc.w += v.w;
        }
        __shared__ float4 red[8][32];
        red[grp][lane] = acc;
        __syncthreads();
        if (grp == 0) {
            float4 t = red[0][lane];
            #pragma unroll
            for (int p = 1; p < 8; ++p) {
                float4 v = red[p][lane];
                t.x += v.x; t.y += v.y; t.z += v.z; t.w += v.w;
            }
            g_s4[j4] = t;
        }
        __syncthreads();
        if (tid == 0) { __threadfence(); atomicAdd(&g_ctr1, 1u); }
    } else {
        // Role B: mask[c] = sigmoid(beta*(dot(s, w_c) + b_c))
        const int c = bid - RED_BLKS;
        const float4* __restrict__ w4 = conv_w4 + (size_t)c * KVOL4;

        // Register prefetch of w (constant trip count, no spill) overlaps the
        // 9.4 MB conv_w read with the ssty reduce.
        float4 wv[5];
        #pragma unroll
        for (int k = 0; k < 5; ++k) {
            int j = tid + k * 256;
            wv[k] = (j < KVOL4) ? w4[j] : make_float4(0.f, 0.f, 0.f, 0.f);
        }

        if (tid == 0) {
            volatile unsigned* p = &g_ctr1;
            while (*p < RED_BLKS) __nanosleep(32);
            __threadfence();
        }
        __syncthreads();

        float acc = 0.0f;
        #pragma unroll
        for (int k = 0; k < 5; ++k) {
            int j = tid + k * 256;
            if (j < KVOL4) {
                float4 s = g_s4[j];
                acc += wv[k].x * s.x + wv[k].y * s.y
                     + wv[k].z * s.z + wv[k].w * s.w;
            }
        }
        #pragma unroll
        for (int off = 16; off > 0; off >>= 1)
            acc += __shfl_down_sync(0xFFFFFFFFu, acc, off);
        __shared__ float red[8];
        if ((tid & 31) == 0) red[tid >> 5] = acc;
        __syncthreads();
        if (tid == 0) {
            float s = 0.0f;
            #pragma unroll
            for (int i = 0; i < 8; ++i) s += red[i];
            float m   = (s + conv_b[c]) * beta[0];
            float msk = 1.0f / (1.0f + expf(-m));
            g_mask[c] = msk;
            if (write_tail) mask_tail[c] = msk;
        }
    }
}

// ── Kernel 2: out = x * mask[channel], PDL-overlapped with mask_kernel ──────
// Launched with programmatic stream serialization: the grid goes resident
// while mask_kernel still runs; each block prefetches x into registers, then
// the HW grid-dependency wait releases it once mask_kernel completes.
__global__ void __launch_bounds__(256)
scale_x_kernel(const float4* __restrict__ x, float4* __restrict__ out) {
    const unsigned base = blockIdx.x * 1024u + threadIdx.x;

    // Prefetch before the dependency wait — overlaps with mask_kernel.
    float4 v0 = __ldcs(x + base);
    float4 v1 = __ldcs(x + base + 256u);
    float4 v2 = __ldcs(x + base + 512u);
    float4 v3 = __ldcs(x + base + 768u);

    cudaGridDependencySynchronize();   // all mask_kernel writes now visible

    if (blockIdx.x == 0 && threadIdx.x == 0) g_ctr1 = 0;  // reset for replay

    float m0 = g_mask[(base          / HW4) & (C_CH - 1)];
    float m1 = g_mask[((base + 256u) / HW4) & (C_CH - 1)];
    float m2 = g_mask[((base + 512u) / HW4) & (C_CH - 1)];
    float m3 = g_mask[((base + 768u) / HW4) & (C_CH - 1)];

    v0.x *= m0; v0.y *= m0; v0.z *= m0; v0.w *= m0;
    v1.x *= m1; v1.y *= m1; v1.z *= m1; v1.w *= m1;
    v2.x *= m2; v2.y *= m2; v2.z *= m2; v2.w *= m2;
    v3.x *= m3; v3.y *= m3; v3.z *= m3; v3.w *= m3;

    __stcs(out + base,        v0);
    __stcs(out + base + 256u, v1);
    __stcs(out + base + 512u, v2);
    __stcs(out + base + 768u, v3);
}

extern "C" void kernel_launch(void* const* d_in, const int* in_sizes, int n_in,
                              void* d_out, int out_size) {
    const float* x      = (const float*)d_in[0];
    const float* ssty   = (const float*)d_in[1];
    const float* beta   = (const float*)d_in[2];
    const float* conv_w = (const float*)d_in[3];
    const float* conv_b = (const float*)d_in[4];
    float* out = (float*)d_out;

    int write_tail = (out_size > (int)NTOT) ? 1 : 0;

    mask_kernel<<<RED_BLKS + DOT_BLKS, 256>>>((const float4*)ssty, beta,
                                              (const float4*)conv_w, conv_b,
                                              out + NTOT, write_tail);

    // Secondary launch with programmatic dependent launch (PDL).
    cudaLaunchConfig_t cfg = {};
    cfg.gridDim  = dim3(N4 / 1024u);
    cfg.blockDim = dim3(256);
    cfg.dynamicSmemBytes = 0;
    cfg.stream = 0;  // legacy default stream (same as <<<>>> above)
    cudaLaunchAttribute attrs[1];
    attrs[0].id = cudaLaunchAttributeProgrammaticStreamSerialization;
    attrs[0].val.programmaticStreamSerializationAllowed = 1;
    cfg.attrs = attrs;
    cfg.numAttrs = 1;
    cudaLaunchKernelEx(&cfg, scale_x_kernel, (const float4*)x, (float4*)out);
}